// round 14
// baseline (speedup 1.0000x reference)
#include <cuda_runtime.h>
#include <cuda_bf16.h>
#include <cstdint>
#include <cstddef>

// ---------------------------------------------------------------------------
// Neural CDE classifier, ONE persistent clustered kernel, bf16 mma.sync
// (3-pass hi/lo ~ fp32) for L1 + W2 GEMMs.
// R14: FOUR independent streams per CTA (8 batch cols, 4 warps each), each
// with private mbarriers + named barrier. 4-way wait/compute overlap.
// W2 warp = 64 W2-rows (2 model rows); B-fragments shared across m-tiles.
// grid = 128 CTAs = 16 clusters x 8, 512 thr/CTA, 1 CTA/SM.
// ---------------------------------------------------------------------------

typedef unsigned long long ull;

namespace {
constexpr int NSTEPS = 2047;
constexpr int KP2 = 272;        // A-operand row stride in BYTES (136 bf16)

// byte offsets in dynamic smem
constexpr int SB_AH  = 0;       // 69632  W2 hi bf16 [256][136]
constexpr int SB_AL  = 69632;   // 69632  W2 lo
constexpr int SB_W1H = 139264;  // 17408  W1-slice hi bf16 [64][136]
constexpr int SB_W1L = 156672;  // 17408  W1-slice lo
constexpr int SB_PK  = 174080;  // 18432  packed u32 (hi|lo) [128][36]: h0, then h1 own half
constexpr int SB_PK2 = 192512;  // 8704   peer h1 half, packed u32 [64][34]
constexpr int SB_W0  = 201216;  // 4096   fp32 W0 slice [16][64]
constexpr int SB_YIN = 205312;  // 8192   yin/y [64][32] fp32
constexpr int SB_KC  = 213504;  // 8192   k [64][32] fp32
constexpr int SB_DX  = 221696;  // 4352   dx [32][34] fp32
constexpr int SB_MB  = 226048;  // 96     12 mbarriers (h0 x4, h1 x4, k x4)
constexpr int SMEM_BYTES = 226144;

constexpr uint32_t TX_H0 = 4096;   // per-stream bytes/substep at each CTA
constexpr uint32_t TX_H1 = 2048;
constexpr uint32_t TX_K  = 2048;
}

__device__ __forceinline__ uint32_t s2u(const void* p) {
    return (uint32_t)__cvta_generic_to_shared(p);
}
__device__ __forceinline__ uint32_t mapa_u(uint32_t laddr, int rank) {
    uint32_t r;
    asm("mapa.shared::cluster.u32 %0, %1, %2;" : "=r"(r) : "r"(laddr), "r"(rank));
    return r;
}
__device__ __forceinline__ void sta_f4(uint32_t raddr, uint32_t rmbar,
                                       float a, float b, float c, float d) {
    asm volatile(
        "st.async.shared::cluster.mbarrier::complete_tx::bytes.v4.f32 "
        "[%0], {%1,%2,%3,%4}, [%5];"
        :: "r"(raddr), "f"(a), "f"(b), "f"(c), "f"(d), "r"(rmbar) : "memory");
}
__device__ __forceinline__ void sta_u4(uint32_t raddr, uint32_t rmbar,
                                       uint32_t a, uint32_t b, uint32_t c, uint32_t d) {
    asm volatile(
        "st.async.shared::cluster.mbarrier::complete_tx::bytes.v4.b32 "
        "[%0], {%1,%2,%3,%4}, [%5];"
        :: "r"(raddr), "r"(a), "r"(b), "r"(c), "r"(d), "r"(rmbar) : "memory");
}
__device__ __forceinline__ void sta_u2(uint32_t raddr, uint32_t rmbar, uint32_t a, uint32_t b) {
    ull v;
    asm("mov.b64 %0, {%1, %2};" : "=l"(v) : "r"(a), "r"(b));
    asm volatile(
        "st.async.shared::cluster.mbarrier::complete_tx::bytes.b64 [%0], %1, [%2];"
        :: "r"(raddr), "l"(v), "r"(rmbar) : "memory");
}
__device__ __forceinline__ void mbar_init(uint32_t mbar, uint32_t cnt) {
    asm volatile("mbarrier.init.shared.b64 [%0], %1;" :: "r"(mbar), "r"(cnt) : "memory");
}
__device__ __forceinline__ void mbar_expect(uint32_t mbar, uint32_t bytes) {
    asm volatile("mbarrier.arrive.expect_tx.shared.b64 _, [%0], %1;"
                 :: "r"(mbar), "r"(bytes) : "memory");
}
__device__ __forceinline__ void mbar_wait(uint32_t mbar, uint32_t parity) {
    asm volatile(
        "{\n\t.reg .pred P;\n\t"
        "WL_%=:\n\t"
        "mbarrier.try_wait.parity.acquire.cluster.shared::cta.b64 P, [%0], %1, 0x989680;\n\t"
        "@!P bra WL_%=;\n\t}"
        :: "r"(mbar), "r"(parity) : "memory");
}
__device__ __forceinline__ void cluster_sync_() {
    asm volatile("barrier.cluster.arrive.aligned;" ::: "memory");
    asm volatile("barrier.cluster.wait.aligned;" ::: "memory");
}
__device__ __forceinline__ void bar_g(int barid) {
    asm volatile("bar.sync %0, %1;" :: "r"(barid), "r"(128) : "memory");
}
__device__ __forceinline__ uint32_t prmt(uint32_t a, uint32_t b, uint32_t sel) {
    uint32_t d;
    asm("prmt.b32 %0, %1, %2, %3;" : "=r"(d) : "r"(a), "r"(b), "r"(sel));
    return d;
}
__device__ __forceinline__ float tanh_f(float x) {
    float ax = fabsf(x);
    float e  = __expf(-2.0f * ax);
    float r  = __fdividef(1.0f - e, 1.0f + e);
    return copysignf(r, x);
}
__device__ __forceinline__ float gelu_f(float x) {
    float x3 = x * x * x;
    float t  = tanh_f(0.7978845608028654f * fmaf(0.044715f, x3, x));
    return 0.5f * x * (1.0f + t);
}
__device__ __forceinline__ uint32_t pack_hilo(float a) {
    __nv_bfloat16 hb = __float2bfloat16(a);
    float hf = __bfloat162float(hb);
    __nv_bfloat16 lb = __float2bfloat16(a - hf);
    return (uint32_t)reinterpret_cast<unsigned short&>(hb) |
           ((uint32_t)reinterpret_cast<unsigned short&>(lb) << 16);
}
__device__ __forceinline__ void ldsm4(uint32_t (&r)[4], uint32_t addr) {
    asm volatile("ldmatrix.sync.aligned.m8n8.x4.shared.b16 {%0,%1,%2,%3}, [%4];"
                 : "=r"(r[0]), "=r"(r[1]), "=r"(r[2]), "=r"(r[3]) : "r"(addr));
}
__device__ __forceinline__ void mma16816(float (&c)[4], const uint32_t (&a)[4],
                                         uint32_t b0, uint32_t b1) {
    asm volatile(
        "mma.sync.aligned.m16n8k16.row.col.f32.bf16.bf16.f32 "
        "{%0,%1,%2,%3}, {%4,%5,%6,%7}, {%8,%9}, {%0,%1,%2,%3};"
        : "+f"(c[0]), "+f"(c[1]), "+f"(c[2]), "+f"(c[3])
        : "r"(a[0]), "r"(a[1]), "r"(a[2]), "r"(a[3]), "r"(b0), "r"(b1));
}

__global__ void __launch_bounds__(512, 1)
ncde_kernel(const float* __restrict__ xs,
            const float* __restrict__ eW0, const float* __restrict__ eb0,
            const float* __restrict__ eW1, const float* __restrict__ eb1,
            const float* __restrict__ eW2, const float* __restrict__ eb2,
            const float* __restrict__ vW0, const float* __restrict__ vb0,
            const float* __restrict__ vW1, const float* __restrict__ vb1,
            const float* __restrict__ vW2, const float* __restrict__ vb2,
            const float* __restrict__ dW,  const float* __restrict__ db,
            float* __restrict__ out)
{
    extern __shared__ char smc[];
    const int tid   = threadIdx.x;
    const int lane  = tid & 31;
    const int wid   = tid >> 5;          // 0..15
    const int gid   = wid >> 2;          // stream id (0..3)
    const int wl    = wid & 3;           // warp id within stream
    const int cb    = gid * 8;           // batch column base of this stream
    const int barid = 1 + gid;
    const int rank  = blockIdx.x & 7;
    const int half_ = rank & 1;
    const int bbase = (blockIdx.x >> 3) * 32;

    float* sW0 = (float*)(smc + SB_W0);
    float* sYI = (float*)(smc + SB_YIN);
    float* sKC = (float*)(smc + SB_KC);
    float* sDX = (float*)(smc + SB_DX);
    uint32_t* sPKw = (uint32_t*)(smc + SB_PK);
    const uint32_t* sP2w = (const uint32_t*)(smc + SB_PK2);

    const uint32_t smem_u = s2u(smc);
    const uint32_t mbH0 = smem_u + SB_MB +      gid * 8;
    const uint32_t mbH1 = smem_u + SB_MB + 32 + gid * 8;
    const uint32_t mbK  = smem_u + SB_MB + 64 + gid * 8;

    if (tid == 0) {
        #pragma unroll
        for (int i = 0; i < 12; ++i) mbar_init(smem_u + SB_MB + i * 8, 1);
    }

    // per-rank DSMEM address deltas (mapa is affine in the local address)
    uint32_t rdelta[8];
    #pragma unroll
    for (int r = 0; r < 8; ++r) rdelta[r] = mapa_u(smem_u, r) - smem_u;
    const uint32_t pdelta = rdelta[rank ^ 1];

    // xs mapping: thread owns (b = tid>>4, d = 2*(tid&15), +1); each stream's
    // threads own exactly that stream's 8 batch columns.
    const int xb  = tid >> 4;
    const int xd2 = tid & 15;
    const float* xsrow = xs + (size_t)(bbase + xb) * 2048 * 32 + xd2 * 2;

    float xc0, xc1;
    {
        float2 v = *reinterpret_cast<const float2*>(xsrow);
        xc0 = v.x; xc1 = v.y;
        sKC[(2 * xd2) * 32 + xb]     = v.x;   // stage xs0 d-major for encoder
        sKC[(2 * xd2 + 1) * 32 + xb] = v.y;
    }

    // ---- encoder weights transposed into W2 scratch region (floats) ----
    float* sE0 = (float*)(smc + SB_AH);          // [32][128]
    float* sE1 = sE0 + 4096;                     // [128][128]
    float* sE2 = sE0 + 20480;                    // [128][64]
    float* sEH = sE0 + 28672;                    // [128][32]
    float* sH0e = (float*)(smc + SB_PK);         // [128][32] encoder hidden1
    for (int i = tid; i < 4096;  i += 512) { int r = i & 127, kk = i >> 7; sE0[i] = eW0[r * 32  + kk]; }
    for (int i = tid; i < 16384; i += 512) { int r = i & 127, kk = i >> 7; sE1[i] = eW1[r * 128 + kk]; }
    for (int i = tid; i < 8192;  i += 512) { int r = i & 63,  kk = i >> 6; sE2[i] = eW2[r * 128 + kk]; }
    __syncthreads();

    // ---- encoder (replicated per CTA): sKC(xs0) -> sH0e -> sEH -> sYI ----
    {
        int b = lane, rbase = wid * 8;
        float acc[8];
        #pragma unroll
        for (int j = 0; j < 8; ++j) acc[j] = eb0[rbase + j];
        for (int kk = 0; kk < 32; ++kk) {
            float x = sKC[kk * 32 + b];
            #pragma unroll
            for (int j = 0; j < 8; ++j) acc[j] = fmaf(sE0[kk * 128 + rbase + j], x, acc[j]);
        }
        #pragma unroll
        for (int j = 0; j < 8; ++j) sH0e[(rbase + j) * 32 + b] = fmaxf(acc[j], 0.0f);
    }
    __syncthreads();
    {
        int b = lane, rbase = wid * 8;
        float acc[8];
        #pragma unroll
        for (int j = 0; j < 8; ++j) acc[j] = eb1[rbase + j];
        for (int kk = 0; kk < 128; ++kk) {
            float x = sH0e[kk * 32 + b];
            #pragma unroll
            for (int j = 0; j < 8; ++j) acc[j] = fmaf(sE1[kk * 128 + rbase + j], x, acc[j]);
        }
        #pragma unroll
        for (int j = 0; j < 8; ++j) sEH[(rbase + j) * 32 + b] = fmaxf(acc[j], 0.0f);
    }
    __syncthreads();
    {
        int b = lane, rbase = wid * 4;
        float acc[4];
        #pragma unroll
        for (int j = 0; j < 4; ++j) acc[j] = eb2[rbase + j];
        for (int kk = 0; kk < 128; ++kk) {
            float x = sEH[kk * 32 + b];
            #pragma unroll
            for (int j = 0; j < 4; ++j) acc[j] = fmaf(sE2[kk * 64 + rbase + j], x, acc[j]);
        }
        #pragma unroll
        for (int j = 0; j < 4; ++j) sYI[(rbase + j) * 32 + b] = acc[j];
    }
    __syncthreads();

    // ---- build static bf16 hi/lo operands (overwrites encoder scratch) ----
    for (int i = tid; i < 32768; i += 512) {        // W2 slice [256 m][128 k]
        int m = i >> 7, k = i & 127;
        float w = vW2[(size_t)(rank * 256 + m) * 128 + k];
        __nv_bfloat16 hb = __float2bfloat16(w);
        float hf = __bfloat162float(hb);
        __nv_bfloat16 lb = __float2bfloat16(w - hf);
        *(__nv_bfloat16*)(smc + SB_AH + m * KP2 + k * 2) = hb;
        *(__nv_bfloat16*)(smc + SB_AL + m * KP2 + k * 2) = lb;
    }
    for (int i = tid; i < 8192; i += 512) {         // W1 slice [64 m][128 k]
        int m = i >> 7, k = i & 127;
        float w = vW1[(size_t)(half_ * 64 + m) * 128 + k];
        __nv_bfloat16 hb = __float2bfloat16(w);
        float hf = __bfloat162float(hb);
        __nv_bfloat16 lb = __float2bfloat16(w - hf);
        *(__nv_bfloat16*)(smc + SB_W1H + m * KP2 + k * 2) = hb;
        *(__nv_bfloat16*)(smc + SB_W1L + m * KP2 + k * 2) = lb;
    }
    for (int i = tid; i < 1024; i += 512) {         // W0 slice fp32 [16][64]
        int kk = i & 63, r = i >> 6;
        sW0[i] = vW0[(rank * 16 + r) * 64 + kk];
    }

    __syncthreads();
    if (tid == 0) {
        #pragma unroll
        for (int gq = 0; gq < 4; ++gq) {
            mbar_expect(smem_u + SB_MB +      gq * 8, TX_H0);
            mbar_expect(smem_u + SB_MB + 32 + gq * 8, TX_H1);
            mbar_expect(smem_u + SB_MB + 64 + gq * 8, TX_K);
        }
    }
    cluster_sync_();

    // ---- per-thread invariants ----
    const int g  = lane >> 2;
    const int tg = lane & 3;

    // L0: warp wl computes h0 rows wl*4 + (lane>>3), col cb + (lane&7)
    const int row0 = wl * 4 + (lane >> 3);
    const int cL0  = lane & 7;
    const float b0s = vb0[rank * 16 + row0];
    const float* wrow0 = sW0 + row0 * 64;
    const uint32_t aPK0 = smem_u + SB_PK + (uint32_t)((rank * 16 + row0) * 36 + cb + cL0) * 4;

    // L1-MMA: warp wl = m-tile wl (16 W1 rows), N = 8 (stream width)
    const float b1a = vb1[half_ * 64 + wl * 16 + g];
    const float b1b = vb1[half_ * 64 + wl * 16 + g + 8];
    const uint32_t aW1H = smem_u + SB_W1H + (uint32_t)(wl * 16 + (lane & 15)) * KP2 + (lane >> 4) * 16;
    const uint32_t aW1L = aW1H + (SB_W1L - SB_W1H);
    const uint32_t* pkL1 = sPKw + tg * 72 + cb + g;

    // h1 outputs
    const int m0r = wl * 16 + g;
    const int c1  = cb + tg * 2;
    ull* h1loc0 = (ull*)(sPKw + (half_ * 64 + m0r) * 36 + c1);
    ull* h1loc1 = (ull*)(sPKw + (half_ * 64 + m0r + 8) * 36 + c1);
    const uint32_t aP2a = smem_u + SB_PK2 + (uint32_t)(m0r * 34 + c1) * 4;
    const uint32_t aP2b = aP2a + 8 * 34 * 4;

    // W2-MMA: warp wl covers local W2 rows wl*64 .. +63 (4 m16 tiles)
    uint32_t aA[4], aAl[4];
    #pragma unroll
    for (int mt = 0; mt < 4; ++mt) {
        aA[mt]  = smem_u + SB_AH + (uint32_t)(wl * 64 + mt * 16 + (lane & 15)) * KP2 + (lane >> 4) * 16;
        aAl[mt] = aA[mt] + (SB_AL - SB_AH);
    }
    const uint32_t* pkOwn  = sPKw + half_ * 2304 + tg * 72 + cb + g;
    const uint32_t* pkPeer = sP2w + tg * 68 + cb + g;
    const int ksOwn  = half_ * 4;
    const int ksPeer = (1 - half_) * 4;

    // epilogue invariants
    float b2r[4][2];
    #pragma unroll
    for (int mt = 0; mt < 4; ++mt) {
        b2r[mt][0] = vb2[rank * 256 + wl * 64 + mt * 16 + g];
        b2r[mt][1] = vb2[rank * 256 + wl * 64 + mt * 16 + g + 8];
    }
    const float* dxb = sDX + g * 34 + cb + tg * 2;
    const uint32_t aKC = smem_u + SB_KC + (uint32_t)((rank * 8 + wl * 2) * 32 + cb) * 4 + (lane >> 1) * 16;

    // RK4 ownership: stream thread ti owns y row ti>>1, cols cb + (ti&1)*4 ..+3
    const int ti = wl * 32 + lane;
    const int ybase = (ti >> 1) * 32 + cb + (ti & 1) * 4;
    float y0 = sYI[ybase + 0], y1 = sYI[ybase + 1];
    float y2 = sYI[ybase + 2], y3 = sYI[ybase + 3];

    uint32_t ph = 0;
    float2 xnA = *reinterpret_cast<const float2*>(xsrow + (size_t)1 * 32);
    float2 xnB = *reinterpret_cast<const float2*>(xsrow + (size_t)2 * 32);

    // ---- main RK4 scan ----
    for (int t = 0; t < NSTEPS; ++t) {
        float2 xn = xnA;
        {
            int tn = (t + 3 <= 2047) ? (t + 3) : 2047;
            xnA = xnB;
            xnB = *reinterpret_cast<const float2*>(xsrow + (size_t)tn * 32);
        }
        float ks0, ks1, ks2, ks3;

        #pragma unroll
        for (int s = 0; s < 4; ++s) {
            // ---- L0: h0[row0][cb+cL0] = gelu(W0row . yin + b0), packed push
            {
                float a = b0s;
                #pragma unroll
                for (int k4 = 0; k4 < 16; ++k4) {
                    float4 w4 = *reinterpret_cast<const float4*>(wrow0 + k4 * 4);
                    a = fmaf(w4.x, sYI[(k4 * 4 + 0) * 32 + cb + cL0], a);
                    a = fmaf(w4.y, sYI[(k4 * 4 + 1) * 32 + cb + cL0], a);
                    a = fmaf(w4.z, sYI[(k4 * 4 + 2) * 32 + cb + cL0], a);
                    a = fmaf(w4.w, sYI[(k4 * 4 + 3) * 32 + cb + cL0], a);
                }
                uint32_t w = pack_hilo(gelu_f(a));
                uint32_t w1 = __shfl_down_sync(0xffffffffu, w, 1);
                uint32_t w2 = __shfl_down_sync(0xffffffffu, w, 2);
                uint32_t w3 = __shfl_down_sync(0xffffffffu, w, 3);
                if ((lane & 3) == 0) {
                    #pragma unroll
                    for (int r = 0; r < 8; ++r)
                        sta_u4(aPK0 + rdelta[r], mbH0 + rdelta[r], w, w1, w2, w3);
                }
            }
            if (s == 0) {   // dx for this step (own-stream columns only)
                float dd0 = xn.x - xc0, dd1 = xn.y - xc1;
                xc0 = xn.x; xc1 = xn.y;
                sDX[(2 * xd2) * 34 + xb]     = dd0;
                sDX[(2 * xd2 + 1) * 34 + xb] = dd1;
            }
            mbar_wait(mbH0, ph);   // packed h0 complete everywhere

            // ---- L1 via MMA (3-pass hi/lo) ----
            float c[4] = {0.0f, 0.0f, 0.0f, 0.0f};
            #pragma unroll
            for (int kk = 0; kk < 8; ++kk) {
                uint32_t ah[4], al[4];
                ldsm4(ah, aW1H + kk * 32);
                ldsm4(al, aW1L + kk * 32);
                const uint32_t* pkk = pkL1 + kk * 576;
                uint32_t w0 = pkk[0],   w1 = pkk[36];
                uint32_t w8 = pkk[288], w9 = pkk[324];
                uint32_t bh0 = prmt(w0, w1, 0x5410u);
                uint32_t bl0 = prmt(w0, w1, 0x7632u);
                uint32_t bh1 = prmt(w8, w9, 0x5410u);
                uint32_t bl1 = prmt(w8, w9, 0x7632u);
                mma16816(c, ah, bh0, bh1);
                mma16816(c, ah, bl0, bl1);
                mma16816(c, al, bh0, bh1);
            }
            uint32_t p0 = pack_hilo(gelu_f(c[0] + b1a));
            uint32_t p1 = pack_hilo(gelu_f(c[1] + b1a));
            uint32_t p2 = pack_hilo(gelu_f(c[2] + b1b));
            uint32_t p3 = pack_hilo(gelu_f(c[3] + b1b));
            bar_g(barid);          // stream done reading h0 (dx also written)
            {
                ull v01, v23;
                asm("mov.b64 %0, {%1, %2};" : "=l"(v01) : "r"(p0), "r"(p1));
                asm("mov.b64 %0, {%1, %2};" : "=l"(v23) : "r"(p2), "r"(p3));
                *h1loc0 = v01;
                *h1loc1 = v23;
                sta_u2(aP2a + pdelta, mbH1 + pdelta, p0, p1);
                sta_u2(aP2b + pdelta, mbH1 + pdelta, p2, p3);
            }
            bar_g(barid);          // own-half h1 visible to whole stream
            mbar_wait(mbH1, ph);   // peer half arrived

            // ---- W2 GEMM: warp = 64 W2-rows (4 m16 tiles), N=8 ----
            float acc[4][4];
            #pragma unroll
            for (int mt = 0; mt < 4; ++mt)
                #pragma unroll
                for (int i = 0; i < 4; ++i) acc[mt][i] = 0.0f;

            #pragma unroll
            for (int k2 = 0; k2 < 4; ++k2) {      // own half k rows
                const uint32_t* pkk = pkOwn + k2 * 576;
                uint32_t w0 = pkk[0],   w1 = pkk[36];
                uint32_t w8 = pkk[288], w9 = pkk[324];
                uint32_t bh0 = prmt(w0, w1, 0x5410u);
                uint32_t bl0 = prmt(w0, w1, 0x7632u);
                uint32_t bh1 = prmt(w8, w9, 0x5410u);
                uint32_t bl1 = prmt(w8, w9, 0x7632u);
                #pragma unroll
                for (int mt = 0; mt < 4; ++mt) {
                    uint32_t ah[4], al[4];
                    ldsm4(ah, aA[mt]  + (ksOwn + k2) * 32);
                    ldsm4(al, aAl[mt] + (ksOwn + k2) * 32);
                    mma16816(acc[mt], ah, bh0, bh1);
                    mma16816(acc[mt], ah, bl0, bl1);
                    mma16816(acc[mt], al, bh0, bh1);
                }
            }
            #pragma unroll
            for (int k2 = 0; k2 < 4; ++k2) {      // peer half k rows
                const uint32_t* pkk = pkPeer + k2 * 544;
                uint32_t w0 = pkk[0],   w1 = pkk[34];
                uint32_t w8 = pkk[272], w9 = pkk[306];
                uint32_t bh0 = prmt(w0, w1, 0x5410u);
                uint32_t bl0 = prmt(w0, w1, 0x7632u);
                uint32_t bh1 = prmt(w8, w9, 0x5410u);
                uint32_t bl1 = prmt(w8, w9, 0x7632u);
                #pragma unroll
                for (int mt = 0; mt < 4; ++mt) {
                    uint32_t ah[4], al[4];
                    ldsm4(ah, aA[mt]  + (ksPeer + k2) * 32);
                    ldsm4(al, aAl[mt] + (ksPeer + k2) * 32);
                    mma16816(acc[mt], ah, bh0, bh1);
                    mma16816(acc[mt], ah, bl0, bl1);
                    mma16816(acc[mt], al, bh0, bh1);
                }
            }

            // ---- epilogue: tanh(+bias)*dx, full d-reduction ----
            {
                float p[2][2] = {{0.0f, 0.0f}, {0.0f, 0.0f}};
                #pragma unroll
                for (int mt = 0; mt < 4; ++mt) {
                    const int mo = mt >> 1;
                    #pragma unroll
                    for (int rp = 0; rp < 2; ++rp) {
                        const float bias = b2r[mt][rp];
                        const float* dxr = dxb + ((mt & 1) * 16 + rp * 8) * 34;
                        float u0 = tanh_f(acc[mt][rp * 2 + 0] + bias);
                        float u1 = tanh_f(acc[mt][rp * 2 + 1] + bias);
                        float2 dx2 = *reinterpret_cast<const float2*>(dxr);
                        p[mo][0] = fmaf(u0, dx2.x, p[mo][0]);
                        p[mo][1] = fmaf(u1, dx2.y, p[mo][1]);
                    }
                }
                #pragma unroll
                for (int m = 4; m <= 16; m <<= 1) {
                    p[0][0] += __shfl_xor_sync(0xffffffffu, p[0][0], m);
                    p[0][1] += __shfl_xor_sync(0xffffffffu, p[0][1], m);
                    p[1][0] += __shfl_xor_sync(0xffffffffu, p[1][0], m);
                    p[1][1] += __shfl_xor_sync(0xffffffffu, p[1][1], m);
                }
                float s00 = __shfl_down_sync(0xffffffffu, p[0][0], 1);
                float s01 = __shfl_down_sync(0xffffffffu, p[0][1], 1);
                float s10 = __shfl_down_sync(0xffffffffu, p[1][0], 1);
                float s11 = __shfl_down_sync(0xffffffffu, p[1][1], 1);
                if (lane == 0 || lane == 2) {
                    #pragma unroll
                    for (int r = 0; r < 8; ++r) {
                        sta_f4(aKC + rdelta[r],       mbK + rdelta[r], p[0][0], p[0][1], s00, s01);
                        sta_f4(aKC + 128 + rdelta[r], mbK + rdelta[r], p[1][0], p[1][1], s10, s11);
                    }
                }
            }
            mbar_wait(mbK, ph);    // stream k complete everywhere
            if (wl == 0 && lane == 0) {   // re-arm this stream's barriers
                mbar_expect(mbH0, TX_H0);
                mbar_expect(mbH1, TX_H1);
                mbar_expect(mbK,  TX_K);
            }

            // ---- RK4 combine (y in registers) ----
            {
                float4 k4 = *reinterpret_cast<const float4*>(&sKC[ybase]);
                if (s == 0) {
                    ks0 = k4.x; ks1 = k4.y; ks2 = k4.z; ks3 = k4.w;
                } else {
                    const float w_s = (s == 3) ? 1.0f : 2.0f;
                    ks0 = fmaf(w_s, k4.x, ks0); ks1 = fmaf(w_s, k4.y, ks1);
                    ks2 = fmaf(w_s, k4.z, ks2); ks3 = fmaf(w_s, k4.w, ks3);
                }
                float4 o;
                if (s < 3) {
                    const float cc = (s == 2) ? 1.0f : 0.5f;
                    o.x = fmaf(cc, k4.x, y0); o.y = fmaf(cc, k4.y, y1);
                    o.z = fmaf(cc, k4.z, y2); o.w = fmaf(cc, k4.w, y3);
                } else {
                    const float sx = 1.0f / 6.0f;
                    y0 = fmaf(sx, ks0, y0); y1 = fmaf(sx, ks1, y1);
                    y2 = fmaf(sx, ks2, y2); y3 = fmaf(sx, ks3, y3);
                    o.x = y0; o.y = y1; o.z = y2; o.w = y3;
                }
                *reinterpret_cast<float4*>(&sYI[ybase]) = o;
            }
            bar_g(barid);          // stream yin visible before next L0
            ph ^= 1;
        }
    }

    __syncthreads();               // all streams' final y in sYI

    // ---- decoder + sigmoid (rank 0 CTA) ----
    if (rank == 0 && tid < 32) {
        float acc = db[0];
        #pragma unroll 8
        for (int r = 0; r < 64; ++r) acc = fmaf(dW[r], sYI[r * 32 + tid], acc);
        out[bbase + tid] = __fdividef(1.0f, 1.0f + __expf(-acc));
    }

    cluster_sync_();  // no CTA exits while peers could still address its smem
}

extern "C" void kernel_launch(void* const* d_in, const int* in_sizes, int n_in,
                              void* d_out, int out_size) {
    (void)in_sizes; (void)n_in; (void)out_size;
    const float* xs  = (const float*)d_in[1];
    const float* eW0 = (const float*)d_in[2];
    const float* eb0 = (const float*)d_in[3];
    const float* eW1 = (const float*)d_in[4];
    const float* eb1 = (const float*)d_in[5];
    const float* eW2 = (const float*)d_in[6];
    const float* eb2 = (const float*)d_in[7];
    const float* vW0 = (const float*)d_in[8];
    const float* vb0 = (const float*)d_in[9];
    const float* vW1 = (const float*)d_in[10];
    const float* vb1 = (const float*)d_in[11];
    const float* vW2 = (const float*)d_in[12];
    const float* vb2 = (const float*)d_in[13];
    const float* dW  = (const float*)d_in[14];
    const float* db  = (const float*)d_in[15];
    float* out = (float*)d_out;

    cudaFuncSetAttribute(ncde_kernel, cudaFuncAttributeMaxDynamicSharedMemorySize, SMEM_BYTES);

    cudaLaunchConfig_t cfg = {};
    cfg.gridDim  = dim3(128, 1, 1);
    cfg.blockDim = dim3(512, 1, 1);
    cfg.dynamicSmemBytes = SMEM_BYTES;
    cfg.stream = 0;
    cudaLaunchAttribute attrs[1];
    attrs[0].id = cudaLaunchAttributeClusterDimension;
    attrs[0].val.clusterDim.x = 8;
    attrs[0].val.clusterDim.y = 1;
    attrs[0].val.clusterDim.z = 1;
    cfg.attrs = attrs;
    cfg.numAttrs = 1;

    cudaLaunchKernelEx(&cfg, ncde_kernel,
                       xs, eW0, eb0, eW1, eb1, eW2, eb2,
                       vW0, vb0, vW1, vb1, vW2, vb2, dW, db, out);
}

// round 15
// speedup vs baseline: 1.0795x; 1.0795x over previous
#include <cuda_runtime.h>
#include <cuda_bf16.h>
#include <cstdint>
#include <cstddef>

// ---------------------------------------------------------------------------
// Neural CDE classifier, ONE persistent clustered kernel, bf16 mma.sync
// (3-pass hi/lo ~ fp32) for L1 + W2 GEMMs.
// R15 = R13 (two independent 16-col streams/CTA) +
//   (1) W2 own-half k-steps execute BEFORE the h1-peer mbar wait (hides the
//       single-peer exchange behind ~half the W2 tensor work);
//   (2) epilogue tanh -> tanh.approx.f32 (halves MUFU on the critical chain).
// grid = 128 CTAs = 16 clusters x 8, 512 thr/CTA, 1 CTA/SM.
// ---------------------------------------------------------------------------

typedef unsigned long long ull;

namespace {
constexpr int NSTEPS = 2047;
constexpr int KP2 = 272;        // A-operand row stride in BYTES (136 bf16)

// byte offsets in dynamic smem
constexpr int SB_AH  = 0;       // 69632  W2 hi bf16 [256][136]
constexpr int SB_AL  = 69632;   // 69632  W2 lo
constexpr int SB_W1H = 139264;  // 17408  W1-slice hi bf16 [64][136]
constexpr int SB_W1L = 156672;  // 17408  W1-slice lo
constexpr int SB_PK  = 174080;  // 18432  packed u32 (hi|lo) [128][36]: h0, then h1 own half
constexpr int SB_PK2 = 192512;  // 8704   peer h1 half, packed u32 [64][34]
constexpr int SB_W0  = 201216;  // 4096   fp32 W0 slice [16][64]
constexpr int SB_YIN = 205312;  // 8192   yin/y [64][32] fp32
constexpr int SB_KC  = 213504;  // 8192   k [64][32] fp32
constexpr int SB_DX  = 221696;  // 4352   dx [32][34] fp32
constexpr int SB_MB  = 226048;  // 48     6 mbarriers (h0 a/b, h1 a/b, k a/b)
constexpr int SMEM_BYTES = 226112;

constexpr uint32_t TX_H0 = 8192;   // per-stream bytes/substep at each CTA
constexpr uint32_t TX_H1 = 4096;
constexpr uint32_t TX_K  = 4096;
}

__device__ __forceinline__ uint32_t s2u(const void* p) {
    return (uint32_t)__cvta_generic_to_shared(p);
}
__device__ __forceinline__ uint32_t mapa_u(uint32_t laddr, int rank) {
    uint32_t r;
    asm("mapa.shared::cluster.u32 %0, %1, %2;" : "=r"(r) : "r"(laddr), "r"(rank));
    return r;
}
__device__ __forceinline__ void sta_f4(uint32_t raddr, uint32_t rmbar,
                                       float a, float b, float c, float d) {
    asm volatile(
        "st.async.shared::cluster.mbarrier::complete_tx::bytes.v4.f32 "
        "[%0], {%1,%2,%3,%4}, [%5];"
        :: "r"(raddr), "f"(a), "f"(b), "f"(c), "f"(d), "r"(rmbar) : "memory");
}
__device__ __forceinline__ void sta_u4(uint32_t raddr, uint32_t rmbar,
                                       uint32_t a, uint32_t b, uint32_t c, uint32_t d) {
    asm volatile(
        "st.async.shared::cluster.mbarrier::complete_tx::bytes.v4.b32 "
        "[%0], {%1,%2,%3,%4}, [%5];"
        :: "r"(raddr), "r"(a), "r"(b), "r"(c), "r"(d), "r"(rmbar) : "memory");
}
__device__ __forceinline__ void sta_u2(uint32_t raddr, uint32_t rmbar, uint32_t a, uint32_t b) {
    ull v;
    asm("mov.b64 %0, {%1, %2};" : "=l"(v) : "r"(a), "r"(b));
    asm volatile(
        "st.async.shared::cluster.mbarrier::complete_tx::bytes.b64 [%0], %1, [%2];"
        :: "r"(raddr), "l"(v), "r"(rmbar) : "memory");
}
__device__ __forceinline__ void mbar_init(uint32_t mbar, uint32_t cnt) {
    asm volatile("mbarrier.init.shared.b64 [%0], %1;" :: "r"(mbar), "r"(cnt) : "memory");
}
__device__ __forceinline__ void mbar_expect(uint32_t mbar, uint32_t bytes) {
    asm volatile("mbarrier.arrive.expect_tx.shared.b64 _, [%0], %1;"
                 :: "r"(mbar), "r"(bytes) : "memory");
}
__device__ __forceinline__ void mbar_wait(uint32_t mbar, uint32_t parity) {
    asm volatile(
        "{\n\t.reg .pred P;\n\t"
        "WL_%=:\n\t"
        "mbarrier.try_wait.parity.acquire.cluster.shared::cta.b64 P, [%0], %1, 0x989680;\n\t"
        "@!P bra WL_%=;\n\t}"
        :: "r"(mbar), "r"(parity) : "memory");
}
__device__ __forceinline__ void cluster_sync_() {
    asm volatile("barrier.cluster.arrive.aligned;" ::: "memory");
    asm volatile("barrier.cluster.wait.aligned;" ::: "memory");
}
__device__ __forceinline__ void bar_g(int barid) {
    asm volatile("bar.sync %0, %1;" :: "r"(barid), "r"(256) : "memory");
}
__device__ __forceinline__ uint32_t prmt(uint32_t a, uint32_t b, uint32_t sel) {
    uint32_t d;
    asm("prmt.b32 %0, %1, %2, %3;" : "=r"(d) : "r"(a), "r"(b), "r"(sel));
    return d;
}
__device__ __forceinline__ float tanh_f(float x) {
    float ax = fabsf(x);
    float e  = __expf(-2.0f * ax);
    float r  = __fdividef(1.0f - e, 1.0f + e);
    return copysignf(r, x);
}
__device__ __forceinline__ float tanh_a(float x) {
    float y;
    asm("tanh.approx.f32 %0, %1;" : "=f"(y) : "f"(x));
    return y;
}
__device__ __forceinline__ float gelu_f(float x) {
    float x3 = x * x * x;
    float t  = tanh_f(0.7978845608028654f * fmaf(0.044715f, x3, x));
    return 0.5f * x * (1.0f + t);
}
__device__ __forceinline__ uint32_t pack_hilo(float a) {
    __nv_bfloat16 hb = __float2bfloat16(a);
    float hf = __bfloat162float(hb);
    __nv_bfloat16 lb = __float2bfloat16(a - hf);
    return (uint32_t)reinterpret_cast<unsigned short&>(hb) |
           ((uint32_t)reinterpret_cast<unsigned short&>(lb) << 16);
}
__device__ __forceinline__ void ldsm4(uint32_t (&r)[4], uint32_t addr) {
    asm volatile("ldmatrix.sync.aligned.m8n8.x4.shared.b16 {%0,%1,%2,%3}, [%4];"
                 : "=r"(r[0]), "=r"(r[1]), "=r"(r[2]), "=r"(r[3]) : "r"(addr));
}
__device__ __forceinline__ void mma16816(float (&c)[4], const uint32_t (&a)[4],
                                         uint32_t b0, uint32_t b1) {
    asm volatile(
        "mma.sync.aligned.m16n8k16.row.col.f32.bf16.bf16.f32 "
        "{%0,%1,%2,%3}, {%4,%5,%6,%7}, {%8,%9}, {%0,%1,%2,%3};"
        : "+f"(c[0]), "+f"(c[1]), "+f"(c[2]), "+f"(c[3])
        : "r"(a[0]), "r"(a[1]), "r"(a[2]), "r"(a[3]), "r"(b0), "r"(b1));
}

__global__ void __launch_bounds__(512, 1)
ncde_kernel(const float* __restrict__ xs,
            const float* __restrict__ eW0, const float* __restrict__ eb0,
            const float* __restrict__ eW1, const float* __restrict__ eb1,
            const float* __restrict__ eW2, const float* __restrict__ eb2,
            const float* __restrict__ vW0, const float* __restrict__ vb0,
            const float* __restrict__ vW1, const float* __restrict__ vb1,
            const float* __restrict__ vW2, const float* __restrict__ vb2,
            const float* __restrict__ dW,  const float* __restrict__ db,
            float* __restrict__ out)
{
    extern __shared__ char smc[];
    const int tid   = threadIdx.x;
    const int lane  = tid & 31;
    const int wid   = tid >> 5;          // 0..15
    const int gid   = wid >> 3;          // warp-group / stream id (0,1)
    const int wl    = wid & 7;           // warp id within group
    const int cb    = gid * 16;          // batch column base of this stream
    const int barid = 1 + gid;
    const int rank  = blockIdx.x & 7;
    const int half_ = rank & 1;
    const int bbase = (blockIdx.x >> 3) * 32;

    float* sW0 = (float*)(smc + SB_W0);
    float* sYI = (float*)(smc + SB_YIN);
    float* sKC = (float*)(smc + SB_KC);
    float* sDX = (float*)(smc + SB_DX);
    uint32_t* sPKw = (uint32_t*)(smc + SB_PK);
    const uint32_t* sP2w = (const uint32_t*)(smc + SB_PK2);

    const uint32_t smem_u = s2u(smc);
    const uint32_t mbH0 = smem_u + SB_MB +      gid * 8;
    const uint32_t mbH1 = smem_u + SB_MB + 16 + gid * 8;
    const uint32_t mbK  = smem_u + SB_MB + 32 + gid * 8;

    if (tid == 0) {
        #pragma unroll
        for (int i = 0; i < 6; ++i) mbar_init(smem_u + SB_MB + i * 8, 1);
    }

    // per-rank DSMEM address deltas (mapa is affine in the local address)
    uint32_t rdelta[8];
    #pragma unroll
    for (int r = 0; r < 8; ++r) rdelta[r] = mapa_u(smem_u, r) - smem_u;
    const uint32_t pdelta = rdelta[rank ^ 1];

    // xs mapping: thread owns (b = tid>>4, d = 2*(tid&15), +1)
    const int xb  = tid >> 4;
    const int xd2 = tid & 15;
    const float* xsrow = xs + (size_t)(bbase + xb) * 2048 * 32 + xd2 * 2;

    float xc0, xc1;
    {
        float2 v = *reinterpret_cast<const float2*>(xsrow);
        xc0 = v.x; xc1 = v.y;
        sKC[(2 * xd2) * 32 + xb]     = v.x;   // stage xs0 d-major for encoder
        sKC[(2 * xd2 + 1) * 32 + xb] = v.y;
    }

    // ---- encoder weights transposed into W2 scratch region (floats) ----
    float* sE0 = (float*)(smc + SB_AH);          // [32][128]
    float* sE1 = sE0 + 4096;                     // [128][128]
    float* sE2 = sE0 + 20480;                    // [128][64]
    float* sEH = sE0 + 28672;                    // [128][32]
    float* sH0e = (float*)(smc + SB_PK);         // [128][32] encoder hidden1
    for (int i = tid; i < 4096;  i += 512) { int r = i & 127, kk = i >> 7; sE0[i] = eW0[r * 32  + kk]; }
    for (int i = tid; i < 16384; i += 512) { int r = i & 127, kk = i >> 7; sE1[i] = eW1[r * 128 + kk]; }
    for (int i = tid; i < 8192;  i += 512) { int r = i & 63,  kk = i >> 6; sE2[i] = eW2[r * 128 + kk]; }
    __syncthreads();

    // ---- encoder (replicated per CTA): sKC(xs0) -> sH0e -> sEH -> sYI ----
    {
        int b = lane, rbase = wid * 8;
        float acc[8];
        #pragma unroll
        for (int j = 0; j < 8; ++j) acc[j] = eb0[rbase + j];
        for (int kk = 0; kk < 32; ++kk) {
            float x = sKC[kk * 32 + b];
            #pragma unroll
            for (int j = 0; j < 8; ++j) acc[j] = fmaf(sE0[kk * 128 + rbase + j], x, acc[j]);
        }
        #pragma unroll
        for (int j = 0; j < 8; ++j) sH0e[(rbase + j) * 32 + b] = fmaxf(acc[j], 0.0f);
    }
    __syncthreads();
    {
        int b = lane, rbase = wid * 8;
        float acc[8];
        #pragma unroll
        for (int j = 0; j < 8; ++j) acc[j] = eb1[rbase + j];
        for (int kk = 0; kk < 128; ++kk) {
            float x = sH0e[kk * 32 + b];
            #pragma unroll
            for (int j = 0; j < 8; ++j) acc[j] = fmaf(sE1[kk * 128 + rbase + j], x, acc[j]);
        }
        #pragma unroll
        for (int j = 0; j < 8; ++j) sEH[(rbase + j) * 32 + b] = fmaxf(acc[j], 0.0f);
    }
    __syncthreads();
    {
        int b = lane, rbase = wid * 4;
        float acc[4];
        #pragma unroll
        for (int j = 0; j < 4; ++j) acc[j] = eb2[rbase + j];
        for (int kk = 0; kk < 128; ++kk) {
            float x = sEH[kk * 32 + b];
            #pragma unroll
            for (int j = 0; j < 4; ++j) acc[j] = fmaf(sE2[kk * 64 + rbase + j], x, acc[j]);
        }
        #pragma unroll
        for (int j = 0; j < 4; ++j) sYI[(rbase + j) * 32 + b] = acc[j];
    }
    __syncthreads();

    // ---- build static bf16 hi/lo operands (overwrites encoder scratch) ----
    for (int i = tid; i < 32768; i += 512) {        // W2 slice [256 m][128 k]
        int m = i >> 7, k = i & 127;
        float w = vW2[(size_t)(rank * 256 + m) * 128 + k];
        __nv_bfloat16 hb = __float2bfloat16(w);
        float hf = __bfloat162float(hb);
        __nv_bfloat16 lb = __float2bfloat16(w - hf);
        *(__nv_bfloat16*)(smc + SB_AH + m * KP2 + k * 2) = hb;
        *(__nv_bfloat16*)(smc + SB_AL + m * KP2 + k * 2) = lb;
    }
    for (int i = tid; i < 8192; i += 512) {         // W1 slice [64 m][128 k]
        int m = i >> 7, k = i & 127;
        float w = vW1[(size_t)(half_ * 64 + m) * 128 + k];
        __nv_bfloat16 hb = __float2bfloat16(w);
        float hf = __bfloat162float(hb);
        __nv_bfloat16 lb = __float2bfloat16(w - hf);
        *(__nv_bfloat16*)(smc + SB_W1H + m * KP2 + k * 2) = hb;
        *(__nv_bfloat16*)(smc + SB_W1L + m * KP2 + k * 2) = lb;
    }
    for (int i = tid; i < 1024; i += 512) {         // W0 slice fp32 [16][64]
        int kk = i & 63, r = i >> 6;
        sW0[i] = vW0[(rank * 16 + r) * 64 + kk];
    }

    __syncthreads();
    if (tid == 0) {
        mbar_expect(smem_u + SB_MB + 0,  TX_H0);
        mbar_expect(smem_u + SB_MB + 8,  TX_H0);
        mbar_expect(smem_u + SB_MB + 16, TX_H1);
        mbar_expect(smem_u + SB_MB + 24, TX_H1);
        mbar_expect(smem_u + SB_MB + 32, TX_K);
        mbar_expect(smem_u + SB_MB + 40, TX_K);
    }
    cluster_sync_();

    // ---- per-thread invariants ----
    const int g  = lane >> 2;
    const int tg = lane & 3;

    // L0: warp wl computes h0 rows 2wl (lanes 0-15) / 2wl+1 (lanes 16-31),
    // cols cb + (lane&15)
    const int row2 = 2 * wl + (lane >> 4);
    const int cL0  = lane & 15;
    const float b0s = vb0[rank * 16 + row2];
    const float* wrow0 = sW0 + row2 * 64;
    const uint32_t aPK0 = smem_u + SB_PK + (uint32_t)((rank * 16 + row2) * 36 + cb + cL0) * 4;

    // L1-MMA: mtile = wl>>1 (16 W1 rows), ntile = wl&1 (8 cols)
    const int mtile = wl >> 1;
    const int ntile = wl & 1;
    const float b1a = vb1[half_ * 64 + mtile * 16 + g];
    const float b1b = vb1[half_ * 64 + mtile * 16 + g + 8];
    const uint32_t aW1H = smem_u + SB_W1H + (uint32_t)(mtile * 16 + (lane & 15)) * KP2 + (lane >> 4) * 16;
    const uint32_t aW1L = aW1H + (SB_W1L - SB_W1H);
    const uint32_t* pkL1 = sPKw + tg * 72 + cb + ntile * 8 + g;

    // h1 outputs
    const int m0r = mtile * 16 + g;
    const int c1  = cb + ntile * 8 + tg * 2;
    ull* h1loc0 = (ull*)(sPKw + (half_ * 64 + m0r) * 36 + c1);
    ull* h1loc1 = (ull*)(sPKw + (half_ * 64 + m0r + 8) * 36 + c1);
    const uint32_t aP2a = smem_u + SB_PK2 + (uint32_t)(m0r * 34 + c1) * 4;
    const uint32_t aP2b = aP2a + 8 * 34 * 4;

    // W2-MMA: warp wl = model row rank*8+wl; A local rows wl*32 + mt*16 ..
    uint32_t aA[2], aAl[2];
    #pragma unroll
    for (int mt = 0; mt < 2; ++mt) {
        aA[mt] = smem_u + SB_AH + (uint32_t)(wl * 32 + mt * 16 + (lane & 15)) * KP2 + (lane >> 4) * 16;
        aAl[mt] = aA[mt] + (SB_AL - SB_AH);
    }
    const uint32_t* pkOwn  = sPKw + half_ * 2304 + tg * 72 + cb + g;
    const uint32_t* pkPeer = sP2w + tg * 68 + cb + g;
    const int ksOwn  = half_ * 4;
    const int ksPeer = (1 - half_) * 4;

    // epilogue invariants
    float b2r[2][2];
    #pragma unroll
    for (int mt = 0; mt < 2; ++mt) {
        b2r[mt][0] = vb2[rank * 256 + wl * 32 + mt * 16 + g];
        b2r[mt][1] = vb2[rank * 256 + wl * 32 + mt * 16 + g + 8];
    }
    const float* dxb = sDX + g * 34 + cb + tg * 2;
    const uint32_t aKC = smem_u + SB_KC + (uint32_t)((rank * 8 + wl) * 32 + cb) * 4 + (lane >> 1) * 16;

    // RK4 ownership: group thread ti owns y row ti>>2, cols cb + (ti&3)*4 ..+3
    const int ti = wl * 32 + lane;
    const int ybase = (ti >> 2) * 32 + cb + (ti & 3) * 4;
    float y0 = sYI[ybase + 0], y1 = sYI[ybase + 1];
    float y2 = sYI[ybase + 2], y3 = sYI[ybase + 3];

    uint32_t ph = 0;
    float2 xnA = *reinterpret_cast<const float2*>(xsrow + (size_t)1 * 32);
    float2 xnB = *reinterpret_cast<const float2*>(xsrow + (size_t)2 * 32);

    // ---- main RK4 scan ----
    for (int t = 0; t < NSTEPS; ++t) {
        float2 xn = xnA;
        {
            int tn = (t + 3 <= 2047) ? (t + 3) : 2047;
            xnA = xnB;
            xnB = *reinterpret_cast<const float2*>(xsrow + (size_t)tn * 32);
        }
        float ks0, ks1, ks2, ks3;

        #pragma unroll
        for (int s = 0; s < 4; ++s) {
            // ---- L0: h0[row2][cb+cL0] = gelu(W0row . yin + b0), packed push
            {
                float a = b0s;
                #pragma unroll
                for (int k4 = 0; k4 < 16; ++k4) {
                    float4 w4 = *reinterpret_cast<const float4*>(wrow0 + k4 * 4);
                    a = fmaf(w4.x, sYI[(k4 * 4 + 0) * 32 + cb + cL0], a);
                    a = fmaf(w4.y, sYI[(k4 * 4 + 1) * 32 + cb + cL0], a);
                    a = fmaf(w4.z, sYI[(k4 * 4 + 2) * 32 + cb + cL0], a);
                    a = fmaf(w4.w, sYI[(k4 * 4 + 3) * 32 + cb + cL0], a);
                }
                uint32_t w = pack_hilo(gelu_f(a));
                uint32_t w1 = __shfl_down_sync(0xffffffffu, w, 1);
                uint32_t w2 = __shfl_down_sync(0xffffffffu, w, 2);
                uint32_t w3 = __shfl_down_sync(0xffffffffu, w, 3);
                if ((lane & 3) == 0) {
                    #pragma unroll
                    for (int r = 0; r < 8; ++r)
                        sta_u4(aPK0 + rdelta[r], mbH0 + rdelta[r], w, w1, w2, w3);
                }
            }
            if (s == 0) {   // dx for this step (own-stream columns only)
                float dd0 = xn.x - xc0, dd1 = xn.y - xc1;
                xc0 = xn.x; xc1 = xn.y;
                sDX[(2 * xd2) * 34 + xb]     = dd0;
                sDX[(2 * xd2 + 1) * 34 + xb] = dd1;
            }
            mbar_wait(mbH0, ph);   // packed h0 ready everywhere

            // ---- L1 via MMA (3-pass hi/lo) ----
            float c[4] = {0.0f, 0.0f, 0.0f, 0.0f};
            #pragma unroll
            for (int kk = 0; kk < 8; ++kk) {
                uint32_t ah[4], al[4];
                ldsm4(ah, aW1H + kk * 32);
                ldsm4(al, aW1L + kk * 32);
                const uint32_t* pkk = pkL1 + kk * 576;
                uint32_t w0 = pkk[0],   w1 = pkk[36];
                uint32_t w8 = pkk[288], w9 = pkk[324];
                uint32_t bh0 = prmt(w0, w1, 0x5410u);
                uint32_t bl0 = prmt(w0, w1, 0x7632u);
                uint32_t bh1 = prmt(w8, w9, 0x5410u);
                uint32_t bl1 = prmt(w8, w9, 0x7632u);
                mma16816(c, ah, bh0, bh1);
                mma16816(c, ah, bl0, bl1);
                mma16816(c, al, bh0, bh1);
            }
            uint32_t p0 = pack_hilo(gelu_f(c[0] + b1a));
            uint32_t p1 = pack_hilo(gelu_f(c[1] + b1a));
            uint32_t p2 = pack_hilo(gelu_f(c[2] + b1b));
            uint32_t p3 = pack_hilo(gelu_f(c[3] + b1b));
            bar_g(barid);          // group done reading h0 (and dx written)
            {
                ull v01, v23;
                asm("mov.b64 %0, {%1, %2};" : "=l"(v01) : "r"(p0), "r"(p1));
                asm("mov.b64 %0, {%1, %2};" : "=l"(v23) : "r"(p2), "r"(p3));
                *h1loc0 = v01;
                *h1loc1 = v23;
                sta_u2(aP2a + pdelta, mbH1 + pdelta, p0, p1);
                sta_u2(aP2b + pdelta, mbH1 + pdelta, p2, p3);
            }
            bar_g(barid);          // own-half h1 visible to whole group

            // ---- W2 GEMM: OWN-half k-steps first (local h1, no wait) ----
            float acc[2][2][4];
            #pragma unroll
            for (int mt = 0; mt < 2; ++mt)
                #pragma unroll
                for (int nt = 0; nt < 2; ++nt)
                    #pragma unroll
                    for (int i = 0; i < 4; ++i) acc[mt][nt][i] = 0.0f;

            #pragma unroll
            for (int k2 = 0; k2 < 4; ++k2) {      // own half k rows
                uint32_t ah0[4], al0[4], ah1[4], al1[4];
                ldsm4(ah0, aA[0]  + (ksOwn + k2) * 32);
                ldsm4(al0, aAl[0] + (ksOwn + k2) * 32);
                ldsm4(ah1, aA[1]  + (ksOwn + k2) * 32);
                ldsm4(al1, aAl[1] + (ksOwn + k2) * 32);
                const uint32_t* pkk = pkOwn + k2 * 576;
                #pragma unroll
                for (int nt = 0; nt < 2; ++nt) {
                    uint32_t w0 = pkk[nt * 8],       w1 = pkk[nt * 8 + 36];
                    uint32_t w8 = pkk[nt * 8 + 288], w9 = pkk[nt * 8 + 324];
                    uint32_t bh0 = prmt(w0, w1, 0x5410u);
                    uint32_t bl0 = prmt(w0, w1, 0x7632u);
                    uint32_t bh1 = prmt(w8, w9, 0x5410u);
                    uint32_t bl1 = prmt(w8, w9, 0x7632u);
                    mma16816(acc[0][nt], ah0, bh0, bh1);
                    mma16816(acc[0][nt], ah0, bl0, bl1);
                    mma16816(acc[0][nt], al0, bh0, bh1);
                    mma16816(acc[1][nt], ah1, bh0, bh1);
                    mma16816(acc[1][nt], ah1, bl0, bl1);
                    mma16816(acc[1][nt], al1, bh0, bh1);
                }
            }

            mbar_wait(mbH1, ph);   // peer half arrived (hidden behind own half)

            #pragma unroll
            for (int k2 = 0; k2 < 4; ++k2) {      // peer half k rows
                uint32_t ah0[4], al0[4], ah1[4], al1[4];
                ldsm4(ah0, aA[0]  + (ksPeer + k2) * 32);
                ldsm4(al0, aAl[0] + (ksPeer + k2) * 32);
                ldsm4(ah1, aA[1]  + (ksPeer + k2) * 32);
                ldsm4(al1, aAl[1] + (ksPeer + k2) * 32);
                const uint32_t* pkk = pkPeer + k2 * 544;
                #pragma unroll
                for (int nt = 0; nt < 2; ++nt) {
                    uint32_t w0 = pkk[nt * 8],       w1 = pkk[nt * 8 + 34];
                    uint32_t w8 = pkk[nt * 8 + 272], w9 = pkk[nt * 8 + 306];
                    uint32_t bh0 = prmt(w0, w1, 0x5410u);
                    uint32_t bl0 = prmt(w0, w1, 0x7632u);
                    uint32_t bh1 = prmt(w8, w9, 0x5410u);
                    uint32_t bl1 = prmt(w8, w9, 0x7632u);
                    mma16816(acc[0][nt], ah0, bh0, bh1);
                    mma16816(acc[0][nt], ah0, bl0, bl1);
                    mma16816(acc[0][nt], al0, bh0, bh1);
                    mma16816(acc[1][nt], ah1, bh0, bh1);
                    mma16816(acc[1][nt], ah1, bl0, bl1);
                    mma16816(acc[1][nt], al1, bh0, bh1);
                }
            }

            // ---- epilogue: tanh.approx(+bias)*dx, full d-reduction in-warp ----
            {
                float p[4] = {0.0f, 0.0f, 0.0f, 0.0f};
                #pragma unroll
                for (int mt = 0; mt < 2; ++mt)
                    #pragma unroll
                    for (int rp = 0; rp < 2; ++rp) {
                        const float bias = b2r[mt][rp];
                        const float* dxr = dxb + (mt * 16 + rp * 8) * 34;
                        #pragma unroll
                        for (int nt = 0; nt < 2; ++nt) {
                            float u0 = tanh_a(acc[mt][nt][rp * 2 + 0] + bias);
                            float u1 = tanh_a(acc[mt][nt][rp * 2 + 1] + bias);
                            float2 dx2 = *reinterpret_cast<const float2*>(dxr + nt * 8);
                            p[nt * 2 + 0] = fmaf(u0, dx2.x, p[nt * 2 + 0]);
                            p[nt * 2 + 1] = fmaf(u1, dx2.y, p[nt * 2 + 1]);
                        }
                    }
                #pragma unroll
                for (int m = 4; m <= 16; m <<= 1)
                    #pragma unroll
                    for (int i = 0; i < 4; ++i)
                        p[i] += __shfl_xor_sync(0xffffffffu, p[i], m);
                float s0 = __shfl_down_sync(0xffffffffu, p[0], 1);
                float s1 = __shfl_down_sync(0xffffffffu, p[1], 1);
                float s2 = __shfl_down_sync(0xffffffffu, p[2], 1);
                float s3 = __shfl_down_sync(0xffffffffu, p[3], 1);
                if (lane == 0 || lane == 2) {
                    #pragma unroll
                    for (int r = 0; r < 8; ++r) {
                        sta_f4(aKC + rdelta[r],      mbK + rdelta[r], p[0], p[1], s0, s1);
                        sta_f4(aKC + 32 + rdelta[r], mbK + rdelta[r], p[2], p[3], s2, s3);
                    }
                }
            }
            mbar_wait(mbK, ph);    // stream k complete everywhere
            if (wl == 0 && lane == 0) {   // re-arm this stream's barriers
                mbar_expect(mbH0, TX_H0);
                mbar_expect(mbH1, TX_H1);
                mbar_expect(mbK,  TX_K);
            }

            // ---- RK4 combine (y in registers) ----
            {
                float4 k4 = *reinterpret_cast<const float4*>(&sKC[ybase]);
                if (s == 0) {
                    ks0 = k4.x; ks1 = k4.y; ks2 = k4.z; ks3 = k4.w;
                } else {
                    const float w_s = (s == 3) ? 1.0f : 2.0f;
                    ks0 = fmaf(w_s, k4.x, ks0); ks1 = fmaf(w_s, k4.y, ks1);
                    ks2 = fmaf(w_s, k4.z, ks2); ks3 = fmaf(w_s, k4.w, ks3);
                }
                float4 o;
                if (s < 3) {
                    const float cc = (s == 2) ? 1.0f : 0.5f;
                    o.x = fmaf(cc, k4.x, y0); o.y = fmaf(cc, k4.y, y1);
                    o.z = fmaf(cc, k4.z, y2); o.w = fmaf(cc, k4.w, y3);
                } else {
                    const float sx = 1.0f / 6.0f;
                    y0 = fmaf(sx, ks0, y0); y1 = fmaf(sx, ks1, y1);
                    y2 = fmaf(sx, ks2, y2); y3 = fmaf(sx, ks3, y3);
                    o.x = y0; o.y = y1; o.z = y2; o.w = y3;
                }
                *reinterpret_cast<float4*>(&sYI[ybase]) = o;
            }
            bar_g(barid);          // group yin visible before next L0
            ph ^= 1;
        }
    }

    __syncthreads();               // both streams' final y in sYI

    // ---- decoder + sigmoid (rank 0 CTA) ----
    if (rank == 0 && tid < 32) {
        float acc = db[0];
        #pragma unroll 8
        for (int r = 0; r < 64; ++r) acc = fmaf(dW[r], sYI[r * 32 + tid], acc);
        out[bbase + tid] = __fdividef(1.0f, 1.0f + __expf(-acc));
    }

    cluster_sync_();  // no CTA exits while peers could still address its smem
}

extern "C" void kernel_launch(void* const* d_in, const int* in_sizes, int n_in,
                              void* d_out, int out_size) {
    (void)in_sizes; (void)n_in; (void)out_size;
    const float* xs  = (const float*)d_in[1];
    const float* eW0 = (const float*)d_in[2];
    const float* eb0 = (const float*)d_in[3];
    const float* eW1 = (const float*)d_in[4];
    const float* eb1 = (const float*)d_in[5];
    const float* eW2 = (const float*)d_in[6];
    const float* eb2 = (const float*)d_in[7];
    const float* vW0 = (const float*)d_in[8];
    const float* vb0 = (const float*)d_in[9];
    const float* vW1 = (const float*)d_in[10];
    const float* vb1 = (const float*)d_in[11];
    const float* vW2 = (const float*)d_in[12];
    const float* vb2 = (const float*)d_in[13];
    const float* dW  = (const float*)d_in[14];
    const float* db  = (const float*)d_in[15];
    float* out = (float*)d_out;

    cudaFuncSetAttribute(ncde_kernel, cudaFuncAttributeMaxDynamicSharedMemorySize, SMEM_BYTES);

    cudaLaunchConfig_t cfg = {};
    cfg.gridDim  = dim3(128, 1, 1);
    cfg.blockDim = dim3(512, 1, 1);
    cfg.dynamicSmemBytes = SMEM_BYTES;
    cfg.stream = 0;
    cudaLaunchAttribute attrs[1];
    attrs[0].id = cudaLaunchAttributeClusterDimension;
    attrs[0].val.clusterDim.x = 8;
    attrs[0].val.clusterDim.y = 1;
    attrs[0].val.clusterDim.z = 1;
    cfg.attrs = attrs;
    cfg.numAttrs = 1;

    cudaLaunchKernelEx(&cfg, ncde_kernel,
                       xs, eW0, eb0, eW1, eb1, eW2, eb2,
                       vW0, vb0, vW1, vb1, vW2, vb2, dW, db, out);
}